// round 6
// baseline (speedup 1.0000x reference)
#include <cuda_runtime.h>

// Fixed shapes
#define Q     32
#define NCLS  4
#define NVAL  16
#define NSAMP 256          // bs*seq
// weights
#define W_CLASS 1.0f
#define W_BBOX  5.0f
#define W_GIOU  2.0f

struct PredXY { float x0, y0, x1, y1, area; };

__device__ __forceinline__ float sel_logit(const float4& lg, int id)
{
    const float lo = (id & 1) ? lg.y : lg.x;
    const float hi = (id & 1) ? lg.w : lg.z;
    return (id & 2) ? hi : lo;
}

__device__ __forceinline__ float pair_cost(const PredXY& pp, const float4& p,
                                           const float4& t, float cls)
{
    const float l1 = fabsf(p.x - t.x) + fabsf(p.y - t.y)
                   + fabsf(p.z - t.z) + fabsf(p.w - t.w);

    const float tx0 = t.x - 0.5f * t.z, ty0 = t.y - 0.5f * t.w;
    const float tx1 = t.x + 0.5f * t.z, ty1 = t.y + 0.5f * t.w;
    const float area_t = (tx1 - tx0) * (ty1 - ty0);

    const float iw = fmaxf(fminf(pp.x1, tx1) - fmaxf(pp.x0, tx0), 0.0f);
    const float ih = fmaxf(fminf(pp.y1, ty1) - fmaxf(pp.y0, ty0), 0.0f);
    const float inter = iw * ih;
    const float uni   = pp.area + area_t - inter;

    const float ew = fmaxf(fmaxf(pp.x1, tx1) - fminf(pp.x0, tx0), 0.0f);
    const float eh = fmaxf(fmaxf(pp.y1, ty1) - fminf(pp.y0, ty0), 0.0f);
    const float area_e = ew * eh;

    // giou = iou - 1 + uni/area_e : both fast divides independent.
    const float iou  = __fdividef(inter, uni);
    const float giou = (iou - 1.0f) + __fdividef(uni, area_e);

    return W_BBOX * l1 - W_CLASS * cls - W_GIOU * giou;
}

// Thread -> (sample i, query a): computes the full 16-target row.
// 8192 threads as 128 CTAs x 64 threads (full SM spread, 2 warps/SM).
// 19 front-batched independent LDG.128 per thread, 4 STG.128 out.
// Pred-side precompute + the 4 class-logit selects are done ONCE per row.
__global__ __launch_bounds__(64)
void matcher_kernel(const float4* __restrict__ pred_logits,  // [256*Q]
                    const float4* __restrict__ pred_boxes,   // [256*Q]
                    const float4* __restrict__ tgt_boxes,    // [256*Q]
                    const int4*   __restrict__ hand_type,    // [256*Q/4]
                    float4*       __restrict__ out)          // [256*Q*4]
{
    const int gtid = blockIdx.x * 64 + threadIdx.x;    // [0, 8192)
    const int i = gtid >> 5;                           // sample
    const int a = gtid & 31;                           // query

    // Front-batched independent loads (MLP = 19)
    const float4 p  = __ldg(&pred_boxes [i * Q + a]);
    const float4 lg = __ldg(&pred_logits[i * Q + a]);
    const int4 ids0 = __ldg(&hand_type[i * (Q / 4) + 0]);
    const int4 ids1 = __ldg(&hand_type[i * (Q / 4) + 1]);
    const int4 ids2 = __ldg(&hand_type[i * (Q / 4) + 2]);
    const int4 ids3 = __ldg(&hand_type[i * (Q / 4) + 3]);

    float4 tg[NVAL];
#pragma unroll
    for (int b = 0; b < NVAL; b++)
        tg[b] = __ldg(&tgt_boxes[i * Q + b]);

    PredXY pp;
    pp.x0 = p.x - 0.5f * p.z;  pp.y0 = p.y - 0.5f * p.w;
    pp.x1 = p.x + 0.5f * p.z;  pp.y1 = p.y + 0.5f * p.w;
    pp.area = (pp.x1 - pp.x0) * (pp.y1 - pp.y0);

    // Class cost per target id (selects once per row)
    float cls[NVAL];
    cls[ 0] = sel_logit(lg, ids0.x); cls[ 1] = sel_logit(lg, ids0.y);
    cls[ 2] = sel_logit(lg, ids0.z); cls[ 3] = sel_logit(lg, ids0.w);
    cls[ 4] = sel_logit(lg, ids1.x); cls[ 5] = sel_logit(lg, ids1.y);
    cls[ 6] = sel_logit(lg, ids1.z); cls[ 7] = sel_logit(lg, ids1.w);
    cls[ 8] = sel_logit(lg, ids2.x); cls[ 9] = sel_logit(lg, ids2.y);
    cls[10] = sel_logit(lg, ids2.z); cls[11] = sel_logit(lg, ids2.w);
    cls[12] = sel_logit(lg, ids3.x); cls[13] = sel_logit(lg, ids3.y);
    cls[14] = sel_logit(lg, ids3.z); cls[15] = sel_logit(lg, ids3.w);

    float r[NVAL];
#pragma unroll
    for (int b = 0; b < NVAL; b++)
        r[b] = pair_cost(pp, p, tg[b], cls[b]);

    float4* o = &out[gtid * 4];
    o[0] = make_float4(r[ 0], r[ 1], r[ 2], r[ 3]);
    o[1] = make_float4(r[ 4], r[ 5], r[ 6], r[ 7]);
    o[2] = make_float4(r[ 8], r[ 9], r[10], r[11]);
    o[3] = make_float4(r[12], r[13], r[14], r[15]);
}

extern "C" void kernel_launch(void* const* d_in, const int* in_sizes, int n_in,
                              void* d_out, int out_size)
{
    const float4* pred_logits = (const float4*)d_in[0];
    const float4* pred_boxes  = (const float4*)d_in[1];
    const float4* tgt_boxes   = (const float4*)d_in[2];
    const int4*   hand_type   = (const int4*)d_in[3];
    (void)in_sizes; (void)n_in; (void)out_size;

    matcher_kernel<<<128, 64>>>(pred_logits, pred_boxes, tgt_boxes,
                                hand_type, (float4*)d_out);
}

// round 7
// speedup vs baseline: 1.0777x; 1.0777x over previous
#include <cuda_runtime.h>

// Fixed shapes
#define Q     32
#define NCLS  4
#define NVAL  16
#define NSAMP 256          // bs*seq = 8*32
// weights
#define W_CLASS 1.0f
#define W_BBOX  5.0f
#define W_GIOU  2.0f

struct PredXY { float x0, y0, x1, y1, area; };

// Register-resident class select: 2-level SELP tree, no local memory.
__device__ __forceinline__ float sel_logit(const float4& lg, int id)
{
    const float lo = (id & 1) ? lg.y : lg.x;
    const float hi = (id & 1) ? lg.w : lg.z;
    return (id & 2) ? hi : lo;
}

__device__ __forceinline__ float pair_cost(const PredXY& pp, const float4& p,
                                           const float4& t, float cls)
{
    // L1 in cxcywh space
    const float l1 = fabsf(p.x - t.x) + fabsf(p.y - t.y)
                   + fabsf(p.z - t.z) + fabsf(p.w - t.w);

    const float tx0 = t.x - 0.5f * t.z, ty0 = t.y - 0.5f * t.w;
    const float tx1 = t.x + 0.5f * t.z, ty1 = t.y + 0.5f * t.w;
    const float area_t = (tx1 - tx0) * (ty1 - ty0);

    const float iw = fmaxf(fminf(pp.x1, tx1) - fmaxf(pp.x0, tx0), 0.0f);
    const float ih = fmaxf(fminf(pp.y1, ty1) - fmaxf(pp.y0, ty0), 0.0f);
    const float inter = iw * ih;
    const float uni   = pp.area + area_t - inter;

    const float ew = fmaxf(fmaxf(pp.x1, tx1) - fminf(pp.x0, tx0), 0.0f);
    const float eh = fmaxf(fmaxf(pp.y1, ty1) - fminf(pp.y0, ty0), 0.0f);
    const float area_e = ew * eh;

    // giou = iou - 1 + uni/area_e : both fast divides independent,
    // so the two MUFU.RCPs issue back-to-back.
    const float iou  = __fdividef(inter, uni);
    const float giou = (iou - 1.0f) + __fdividef(uni, area_e);

    return W_BBOX * l1 - W_CLASS * cls - W_GIOU * giou;
}

// Thread -> (sample i, query a, 4 consecutive targets). 32768 threads as
// 128 CTAs x 256 threads (measured optimum shape). No smem, no barriers,
// MLP=7 front-batched loads, one STG.128 per thread.
//
// Index algebra: gtid = 128*i + 4*a + bq, so
//   pred/logit index  i*Q + a  == gtid >> 2
//   ids index         i*8 + bq == ((gtid>>7)<<3) | (gtid&3)
//   tgt base          i*Q + 4*bq == ((gtid>>7)<<5) | ((gtid&3)<<2)
__global__ __launch_bounds__(256)
void matcher_kernel(const float4* __restrict__ pred_logits,  // [256*Q] (NCLS=4)
                    const float4* __restrict__ pred_boxes,   // [256*Q]
                    const float4* __restrict__ tgt_boxes,    // [256*Q]
                    const int4*   __restrict__ hand_type,    // [256*Q/4]
                    float4*       __restrict__ out)          // [256*Q*NVAL/4]
{
    const int gtid = blockIdx.x * 256 + threadIdx.x;   // [0, 32768)
    const int pa = gtid >> 2;                          // i*Q + a
    const int ih = gtid >> 7;                          // sample i
    const int bq = gtid & 3;                           // target quad
    const int ib = (ih << 3) | bq;                     // ids index
    const int tb = (ih << 5) | (bq << 2);              // tgt base

    const float4 p   = __ldg(&pred_boxes [pa]);
    const float4 lg  = __ldg(&pred_logits[pa]);
    const int4   ids = __ldg(&hand_type  [ib]);
    const float4 t0 = __ldg(&tgt_boxes[tb + 0]);
    const float4 t1 = __ldg(&tgt_boxes[tb + 1]);
    const float4 t2 = __ldg(&tgt_boxes[tb + 2]);
    const float4 t3 = __ldg(&tgt_boxes[tb + 3]);

    PredXY pp;
    pp.x0 = p.x - 0.5f * p.z;  pp.y0 = p.y - 0.5f * p.w;
    pp.x1 = p.x + 0.5f * p.z;  pp.y1 = p.y + 0.5f * p.w;
    pp.area = (pp.x1 - pp.x0) * (pp.y1 - pp.y0);

    float4 r;
    r.x = pair_cost(pp, p, t0, sel_logit(lg, ids.x));
    r.y = pair_cost(pp, p, t1, sel_logit(lg, ids.y));
    r.z = pair_cost(pp, p, t2, sel_logit(lg, ids.z));
    r.w = pair_cost(pp, p, t3, sel_logit(lg, ids.w));

    out[gtid] = r;
}

extern "C" void kernel_launch(void* const* d_in, const int* in_sizes, int n_in,
                              void* d_out, int out_size)
{
    const float4* pred_logits = (const float4*)d_in[0];
    const float4* pred_boxes  = (const float4*)d_in[1];
    const float4* tgt_boxes   = (const float4*)d_in[2];
    const int4*   hand_type   = (const int4*)d_in[3];
    (void)in_sizes; (void)n_in; (void)out_size;

    matcher_kernel<<<128, 256>>>(pred_logits, pred_boxes, tgt_boxes,
                                 hand_type, (float4*)d_out);
}

// round 8
// speedup vs baseline: 1.0833x; 1.0052x over previous
#include <cuda_runtime.h>

// Fixed shapes
#define Q     32
#define NCLS  4
#define NVAL  16
#define NSAMP 256          // bs*seq = 8*32
// weights
#define W_CLASS 1.0f
#define W_BBOX  5.0f
#define W_GIOU  2.0f

struct PredXY { float x0, y0, x1, y1, area; };

// Register-resident class select: 2-level SELP tree, no local memory.
__device__ __forceinline__ float sel_logit(const float4& lg, int id)
{
    const float lo = (id & 1) ? lg.y : lg.x;
    const float hi = (id & 1) ? lg.w : lg.z;
    return (id & 2) ? hi : lo;
}

__device__ __forceinline__ float pair_cost(const PredXY& pp, const float4& p,
                                           const float4& t, float cls)
{
    // L1 in cxcywh space
    const float l1 = fabsf(p.x - t.x) + fabsf(p.y - t.y)
                   + fabsf(p.z - t.z) + fabsf(p.w - t.w);

    const float tx0 = t.x - 0.5f * t.z, ty0 = t.y - 0.5f * t.w;
    const float tx1 = t.x + 0.5f * t.z, ty1 = t.y + 0.5f * t.w;
    const float area_t = (tx1 - tx0) * (ty1 - ty0);

    const float iw = fmaxf(fminf(pp.x1, tx1) - fmaxf(pp.x0, tx0), 0.0f);
    const float ih = fmaxf(fminf(pp.y1, ty1) - fmaxf(pp.y0, ty0), 0.0f);
    const float inter = iw * ih;
    const float uni   = pp.area + area_t - inter;

    const float ew = fmaxf(fmaxf(pp.x1, tx1) - fminf(pp.x0, tx0), 0.0f);
    const float eh = fmaxf(fmaxf(pp.y1, ty1) - fminf(pp.y0, ty0), 0.0f);
    const float area_e = ew * eh;

    // giou = iou - 1 + uni/area_e : both fast divides independent,
    // so the two MUFU.RCPs issue back-to-back.
    const float iou  = __fdividef(inter, uni);
    const float giou = (iou - 1.0f) + __fdividef(uni, area_e);

    return W_BBOX * l1 - W_CLASS * cls - W_GIOU * giou;
}

// Thread -> (sample i, query a, 4 consecutive targets). 32768 threads as
// 256 CTAs x 128 threads: spreads over all 148 SMs (108 SMs take 2 CTAs),
// identical per-warp work to the 128x256 shape. No smem, no barriers,
// MLP=7 front-batched loads, one STG.128 per thread.
//
// Index algebra: gtid = 128*i + 4*a + bq, so
//   pred/logit index  i*Q + a   == gtid >> 2
//   ids index         i*8 + bq  == ((gtid>>7)<<3) | (gtid&3)
//   tgt base          i*Q + 4bq == ((gtid>>7)<<5) | ((gtid&3)<<2)
__global__ __launch_bounds__(128)
void matcher_kernel(const float4* __restrict__ pred_logits,  // [256*Q] (NCLS=4)
                    const float4* __restrict__ pred_boxes,   // [256*Q]
                    const float4* __restrict__ tgt_boxes,    // [256*Q]
                    const int4*   __restrict__ hand_type,    // [256*Q/4]
                    float4*       __restrict__ out)          // [256*Q*NVAL/4]
{
    const int gtid = blockIdx.x * 128 + threadIdx.x;   // [0, 32768)
    const int pa = gtid >> 2;                          // i*Q + a
    const int ih = gtid >> 7;                          // sample i
    const int bq = gtid & 3;                           // target quad
    const int ib = (ih << 3) | bq;                     // ids index
    const int tb = (ih << 5) | (bq << 2);              // tgt base

    const float4 p   = __ldg(&pred_boxes [pa]);
    const float4 lg  = __ldg(&pred_logits[pa]);
    const int4   ids = __ldg(&hand_type  [ib]);
    const float4 t0 = __ldg(&tgt_boxes[tb + 0]);
    const float4 t1 = __ldg(&tgt_boxes[tb + 1]);
    const float4 t2 = __ldg(&tgt_boxes[tb + 2]);
    const float4 t3 = __ldg(&tgt_boxes[tb + 3]);

    PredXY pp;
    pp.x0 = p.x - 0.5f * p.z;  pp.y0 = p.y - 0.5f * p.w;
    pp.x1 = p.x + 0.5f * p.z;  pp.y1 = p.y + 0.5f * p.w;
    pp.area = (pp.x1 - pp.x0) * (pp.y1 - pp.y0);

    float4 r;
    r.x = pair_cost(pp, p, t0, sel_logit(lg, ids.x));
    r.y = pair_cost(pp, p, t1, sel_logit(lg, ids.y));
    r.z = pair_cost(pp, p, t2, sel_logit(lg, ids.z));
    r.w = pair_cost(pp, p, t3, sel_logit(lg, ids.w));

    out[gtid] = r;
}

extern "C" void kernel_launch(void* const* d_in, const int* in_sizes, int n_in,
                              void* d_out, int out_size)
{
    const float4* pred_logits = (const float4*)d_in[0];
    const float4* pred_boxes  = (const float4*)d_in[1];
    const float4* tgt_boxes   = (const float4*)d_in[2];
    const int4*   hand_type   = (const int4*)d_in[3];
    (void)in_sizes; (void)n_in; (void)out_size;

    matcher_kernel<<<256, 128>>>(pred_logits, pred_boxes, tgt_boxes,
                                 hand_type, (float4*)d_out);
}